// round 14
// baseline (speedup 1.0000x reference)
#include <cuda_runtime.h>
#include <cuda_bf16.h>
#include <cstdint>

// Inputs (metadata order):
//   d_in[0] = z          float32 [12288, 128]
//   d_in[1] = edge_index int32 [2, 393216] (jnp.int64 silently downcast; detect)
//   d_in[2] = edge_attr  float32 [393216, 4]
//   d_in[3] = W          float32 [1, 256]
//   d_in[4] = b          float32 [1]
// Output: float32 [12288, 12288]
//
// out[r,c] = sum_dup(attr_sum) + (u[r]+v[c]+b) once per distinct cell.
// Single mega kernel [UV | EDGE | ZERO] (fold validated in R10/R11: mega~107
// vs 104+6.2 split) + ORDER-PRESERVING hash (validated R13: scatter ~10us,
// stores ascend through DRAM rows):
//   UV:   per-node dots u/v, release g_uv_done (never waits).
//   EDGE: hash-insert cell+1 (atomicCAS election) + atomicAdd; spins on
//         g_uv_done first (deadlock-free: all UV bids dispatch before EDGE).
//   ZERO: grid-stride float4 zero of the 604MB output (validated floor).
// Scatter: sequential slot sweep -> ascending out stores; restores slots and
// re-arms the flag (self-cleaning, graph-replay deterministic).

#define N_NODES 12288
#define N_EDGES 393216

#define UV_BLOCKS    1536   // 8 warps/block -> 12288 warps, one per node
#define EDGE_BLOCKS  1536   // thread per edge
#define ZERO_BLOCKS  4736   // 148 SMs * 32

#define HASH_BITS 20
#define HASH_SIZE (1u << HASH_BITS)         // 1,048,576 slots (load ~0.37)
#define HASH_MASK (HASH_SIZE - 1u)
// floor(2^32 * HASH_SIZE / (N_NODES*N_NODES)) — monotonic multiply-shift
#define HASH_MULT 29826161ull

__device__ int      g_keys[HASH_SIZE];      // cell+1, 0 = empty; zero-init
__device__ float    g_vals[HASH_SIZE];      // accumulated value; zero-init
__device__ float    g_u[N_NODES];           // dot(z[i], W[0:128]) + b
__device__ float    g_v[N_NODES];           // dot(z[i], W[128:256])
__device__ unsigned g_uv_done;              // UV completion counter; zero-init

// ---------------------------------------------------------------------------
__device__ __forceinline__ int block_detect_is64(const int* __restrict__ ei32,
                                                 int* sh_flag) {
    if (threadIdx.x < 32) {
        int w = ei32[2 * threadIdx.x + 1];
        unsigned any = __ballot_sync(0xFFFFFFFFu, w != 0);
        if (threadIdx.x == 0) *sh_flag = (any == 0u) ? 1 : 0;
    }
    __syncthreads();
    return *sh_flag;
}

__device__ __forceinline__ long long load_idx(const void* ei, size_t pos, int is64) {
    if (is64) return ((const long long*)ei)[pos];
    return (long long)((const int*)ei)[pos];
}

// order-preserving initial slot: cell scaled into [0, HASH_SIZE)
__device__ __forceinline__ unsigned hash_slot(unsigned cell) {
    return (unsigned)(((unsigned long long)cell * HASH_MULT) >> 32);
}

// ---------------------------------------------------------------------------
__global__ void mega_kernel(float4* __restrict__ out, size_t n4,
                            const void* __restrict__ ei,
                            const float4* __restrict__ attr,
                            const float* __restrict__ z,
                            const float* __restrict__ W,
                            const float* __restrict__ b) {
    __shared__ int sh_flag;
    int bid = blockIdx.x;

    if (bid < UV_BLOCKS) {
        // ---- u/v precompute: warp-per-node dot, bias folded into u ----
        int node = bid * 8 + (threadIdx.x >> 5);
        int lane = threadIdx.x & 31;
        if (node < N_NODES) {
            float4 zv = reinterpret_cast<const float4*>(z + (size_t)node * 128)[lane];
            float4 w1 = reinterpret_cast<const float4*>(W)[lane];
            float4 w2 = reinterpret_cast<const float4*>(W + 128)[lane];
            float s1 = zv.x * w1.x + zv.y * w1.y + zv.z * w1.z + zv.w * w1.w;
            float s2 = zv.x * w2.x + zv.y * w2.y + zv.z * w2.z + zv.w * w2.w;
            #pragma unroll
            for (int o = 16; o > 0; o >>= 1) {
                s1 += __shfl_xor_sync(0xFFFFFFFFu, s1, o);
                s2 += __shfl_xor_sync(0xFFFFFFFFu, s2, o);
            }
            if (lane == 0) {
                g_u[node] = s1 + b[0];
                g_v[node] = s2;
            }
        }
        __syncthreads();
        if (threadIdx.x == 0) {
            __threadfence();                        // publish u/v before count
            atomicAdd(&g_uv_done, 1u);
        }
    } else if (bid < UV_BLOCKS + EDGE_BLOCKS) {
        // ---- edge scatter into hash ----
        int is64 = block_detect_is64((const int*)ei, &sh_flag);
        int e = (bid - UV_BLOCKS) * 256 + threadIdx.x;

        long long r = 0, c = 0;
        bool valid = (e < N_EDGES);
        if (valid) {
            r = load_idx(ei, e, is64);
            c = load_idx(ei, (size_t)N_EDGES + e, is64);
            valid = ((unsigned long long)r < N_NODES) &&
                    ((unsigned long long)c < N_NODES);
        }
        float4 a = valid ? attr[e] : make_float4(0.f, 0.f, 0.f, 0.f);

        // wait until all UV blocks have published u/v
        if (threadIdx.x == 0) {
            while (atomicAdd(&g_uv_done, 0u) < (unsigned)UV_BLOCKS) { }
            __threadfence();                        // acquire
        }
        __syncthreads();
        if (!valid) return;

        unsigned cell = (unsigned)(r * N_NODES + c);
        int key = (int)cell + 1;                    // 0 reserved for empty
        float add = a.x + a.y + a.z + a.w;

        unsigned h = hash_slot(cell);
        while (true) {
            int prev = atomicCAS(&g_keys[h], 0, key);
            if (prev == 0)  { add += g_u[r] + g_v[c]; break; }   // elected
            if (prev == key) break;                              // duplicate
            h = (h + 1u) & HASH_MASK;
        }
        atomicAdd(&g_vals[h], add);
    } else {
        // ---- zero the output: plain float4 stores (validated floor) ----
        size_t i = (size_t)(bid - UV_BLOCKS - EDGE_BLOCKS) * blockDim.x + threadIdx.x;
        size_t stride = (size_t)ZERO_BLOCKS * blockDim.x;
        float4 zero = make_float4(0.f, 0.f, 0.f, 0.f);
        for (; i < n4; i += stride) out[i] = zero;
    }
}

// ---------------------------------------------------------------------------
// Scatter hash -> out. Sequential slot sweep; order-preserving hash makes
// out stores ascend in address (sequential DRAM rows). Scalar, 1 slot/thread
// (validated best shape). Restores slots + re-arms flag (self-cleaning).
// ---------------------------------------------------------------------------
__global__ void scatter_kernel(float* __restrict__ out) {
    unsigned t = blockIdx.x * 256u + threadIdx.x;
    if (t == 0) g_uv_done = 0;                      // re-arm for next launch
    if (t >= HASH_SIZE) return;
    int k = g_keys[t];
    if (k > 0) {
        out[(size_t)(unsigned)(k - 1)] = g_vals[t];
        g_keys[t] = 0;
        g_vals[t] = 0.0f;
    }
}

// ---------------------------------------------------------------------------
extern "C" void kernel_launch(void* const* d_in, const int* in_sizes, int n_in,
                              void* d_out, int out_size) {
    const float*  z    = (const float*)d_in[0];
    const void*   ei   = d_in[1];
    const float4* attr = (const float4*)d_in[2];
    const float*  W    = (const float*)d_in[3];
    const float*  b    = (const float*)d_in[4];
    float*        out  = (float*)d_out;

    size_t n4 = (size_t)out_size / 4;

    mega_kernel<<<UV_BLOCKS + EDGE_BLOCKS + ZERO_BLOCKS, 256>>>(
        (float4*)out, n4, ei, attr, z, W, b);
    scatter_kernel<<<(HASH_SIZE + 255) / 256, 256>>>(out);
}

// round 15
// speedup vs baseline: 1.0597x; 1.0597x over previous
#include <cuda_runtime.h>
#include <cuda_bf16.h>
#include <cstdint>

// Inputs (metadata order):
//   d_in[0] = z          float32 [12288, 128]
//   d_in[1] = edge_index int32 [2, 393216] (jnp.int64 silently downcast; detect)
//   d_in[2] = edge_attr  float32 [393216, 4]
//   d_in[3] = W          float32 [1, 256]
//   d_in[4] = b          float32 [1]
// Output: float32 [12288, 12288]
//
// out[r,c] = sum_dup(attr_sum) + (u[r]+v[c]+b) once per distinct cell.
// KEY RESTRUCTURE vs R13: the prob term is added in the SCATTER kernel
// (once per occupied hash slot = once per distinct cell), so the edge phase
// never reads u/v => UV needs no ordering vs EDGE. UV folds into mega as a
// tiny 48-block prologue (thread-per-node) that cannot delay the zero wave,
// deleting the separate init launch with zero handshake cost.
//   mega:   [UV(48) | EDGE(1536) | ZERO(4736)], no spins, no flags.
//   scatter: sequential slot sweep (order-preserving hash => ascending out
//            stores), out[cell] = val + u[r] + v[c]; self-cleaning slots.

#define N_NODES 12288
#define N_EDGES 393216

#define UV_BLOCKS    48     // 48*256 = 12288 threads, one per node
#define EDGE_BLOCKS  1536   // thread per edge
#define ZERO_BLOCKS  4736   // 148 SMs * 32

#define HASH_BITS 20
#define HASH_SIZE (1u << HASH_BITS)         // 1,048,576 slots (load ~0.37)
#define HASH_MASK (HASH_SIZE - 1u)
// floor(2^32 * HASH_SIZE / (N_NODES*N_NODES)) — monotonic multiply-shift
#define HASH_MULT 29826161ull

__device__ int   g_keys[HASH_SIZE];         // cell+1, 0 = empty; zero-init
__device__ float g_vals[HASH_SIZE];         // accumulated attr sums; zero-init
__device__ float g_u[N_NODES];              // dot(z[i], W[0:128]) + b
__device__ float g_v[N_NODES];              // dot(z[i], W[128:256])

// ---------------------------------------------------------------------------
__device__ __forceinline__ int block_detect_is64(const int* __restrict__ ei32,
                                                 int* sh_flag) {
    if (threadIdx.x < 32) {
        int w = ei32[2 * threadIdx.x + 1];
        unsigned any = __ballot_sync(0xFFFFFFFFu, w != 0);
        if (threadIdx.x == 0) *sh_flag = (any == 0u) ? 1 : 0;
    }
    __syncthreads();
    return *sh_flag;
}

__device__ __forceinline__ long long load_idx(const void* ei, size_t pos, int is64) {
    if (is64) return ((const long long*)ei)[pos];
    return (long long)((const int*)ei)[pos];
}

// order-preserving initial slot: cell scaled into [0, HASH_SIZE)
__device__ __forceinline__ unsigned hash_slot(unsigned cell) {
    return (unsigned)(((unsigned long long)cell * HASH_MULT) >> 32);
}

// ---------------------------------------------------------------------------
__global__ void mega_kernel(float4* __restrict__ out, size_t n4,
                            const void* __restrict__ ei,
                            const float4* __restrict__ attr,
                            const float* __restrict__ z,
                            const float* __restrict__ W,
                            const float* __restrict__ b) {
    __shared__ int sh_flag;
    int bid = blockIdx.x;

    if (bid < UV_BLOCKS) {
        // ---- u/v: thread-per-node dot, W staged in shared (2KB) ----
        __shared__ float4 sW1[32], sW2[32];
        if (threadIdx.x < 32) {
            sW1[threadIdx.x] = reinterpret_cast<const float4*>(W)[threadIdx.x];
            sW2[threadIdx.x] = reinterpret_cast<const float4*>(W + 128)[threadIdx.x];
        }
        __syncthreads();
        int node = bid * 256 + threadIdx.x;             // exactly covers 12288
        const float4* zrow = reinterpret_cast<const float4*>(z + (size_t)node * 128);
        float s1 = 0.f, s2 = 0.f;
        #pragma unroll
        for (int j = 0; j < 32; ++j) {
            float4 zv = zrow[j];
            float4 w1 = sW1[j], w2 = sW2[j];
            s1 += zv.x * w1.x + zv.y * w1.y + zv.z * w1.z + zv.w * w1.w;
            s2 += zv.x * w2.x + zv.y * w2.y + zv.z * w2.z + zv.w * w2.w;
        }
        g_u[node] = s1 + b[0];                          // bias folded into u
        g_v[node] = s2;
    } else if (bid < UV_BLOCKS + EDGE_BLOCKS) {
        // ---- edge phase: hash insert + attr-sum accumulate (no u/v!) ----
        int is64 = block_detect_is64((const int*)ei, &sh_flag);
        int e = (bid - UV_BLOCKS) * 256 + threadIdx.x;
        if (e >= N_EDGES) return;
        long long r = load_idx(ei, e, is64);
        long long c = load_idx(ei, (size_t)N_EDGES + e, is64);
        if ((unsigned long long)r >= N_NODES || (unsigned long long)c >= N_NODES) return;

        float4 a = attr[e];
        unsigned cell = (unsigned)(r * N_NODES + c);
        int key = (int)cell + 1;                        // 0 reserved for empty
        float add = a.x + a.y + a.z + a.w;

        unsigned h = hash_slot(cell);
        while (true) {
            int prev = atomicCAS(&g_keys[h], 0, key);
            if (prev == 0 || prev == key) break;        // inserted or duplicate
            h = (h + 1u) & HASH_MASK;
        }
        atomicAdd(&g_vals[h], add);
    } else {
        // ---- zero the output: grid-stride float4 (validated floor) ----
        size_t i = (size_t)(bid - UV_BLOCKS - EDGE_BLOCKS) * blockDim.x + threadIdx.x;
        size_t stride = (size_t)ZERO_BLOCKS * blockDim.x;
        float4 zero = make_float4(0.f, 0.f, 0.f, 0.f);
        for (; i < n4; i += stride) out[i] = zero;
    }
}

// ---------------------------------------------------------------------------
// Scatter hash -> out. Sequential slot sweep; order-preserving hash makes out
// stores ascend in address. Adds the prob term HERE, once per distinct cell:
//   out[cell] = val + u[cell/N] + v[cell%N]   (u/v tables are 96KB, L2-hot)
// Restores slots to empty (self-cleaning, graph-replay deterministic).
// ---------------------------------------------------------------------------
__global__ void scatter_kernel(float* __restrict__ out) {
    unsigned t = blockIdx.x * 256u + threadIdx.x;
    if (t >= HASH_SIZE) return;
    int k = g_keys[t];
    if (k > 0) {
        unsigned cell = (unsigned)(k - 1);
        unsigned r = cell / (unsigned)N_NODES;          // const-div -> mul
        unsigned c = cell - r * (unsigned)N_NODES;
        out[(size_t)cell] = g_vals[t] + g_u[r] + g_v[c];
        g_keys[t] = 0;
        g_vals[t] = 0.0f;
    }
}

// ---------------------------------------------------------------------------
extern "C" void kernel_launch(void* const* d_in, const int* in_sizes, int n_in,
                              void* d_out, int out_size) {
    const float*  z    = (const float*)d_in[0];
    const void*   ei   = d_in[1];
    const float4* attr = (const float4*)d_in[2];
    const float*  W    = (const float*)d_in[3];
    const float*  b    = (const float*)d_in[4];
    float*        out  = (float*)d_out;

    size_t n4 = (size_t)out_size / 4;

    mega_kernel<<<UV_BLOCKS + EDGE_BLOCKS + ZERO_BLOCKS, 256>>>(
        (float4*)out, n4, ei, attr, z, W, b);
    scatter_kernel<<<(HASH_SIZE + 255) / 256, 256>>>(out);
}